// round 11
// baseline (speedup 1.0000x reference)
#include <cuda_runtime.h>
#include <cuda_bf16.h>

// out[b,s,d] = in[b,s,d] + pe(s,d)
//   pe(s,d) = sin(s * f(d)) if d even else cos(s * f(d)),  f(d) = 10000^(-2d/D)
//
// B=8, S=4096, D=1024, fp32. 268 MB/launch.
// R10 (45.6us) proved the winning mechanism is READ-ISSUE CONTINUITY: all 8
// next-row loads in flight before the store burst. R11 removes the two
// remaining issue bubbles:
//   1. prefetch hoisted ABOVE the pe MUFU computation (loads issue first
//      each iteration; MUFU latency hides under them),
//   2. loop unrolled x2 with A/N ping-pong (kills the 8-MOV rotation between
//      store bursts).
// Held fixed: grid 592, 3 blocks/SM, .cs loads+stores, float4/256-thread map.

constexpr int D    = 1024;
constexpr int S    = 4096;
constexpr int B    = 8;
constexpr int TPB  = D / 4;       // 256 threads, one float4 of d each
constexpr int GRID = 4 * 148;     // 592 blocks, grid-stride over s
constexpr int SD   = S * TPB;     // float4 stride between batches

__device__ __forceinline__ void store_row(float4* __restrict__ out, int row,
                                          const float4* v, const float4& pe) {
    #pragma unroll
    for (int b = 0; b < B; ++b) {
        float4 o;
        o.x = v[b].x + pe.x; o.y = v[b].y + pe.y;
        o.z = v[b].z + pe.z; o.w = v[b].w + pe.w;
        __stcs(&out[b * SD + row], o);
    }
}

__global__ __launch_bounds__(TPB, 3)
void pe_add_kernel(const float4* __restrict__ in, float4* __restrict__ out) {
    const int d4 = threadIdx.x;
    const int d  = d4 * 4;

    // f(d+j) = exp2( -(d+j) * 2*log2(10000)/1024 ), row-independent
    const float c = -2.0f * 13.287712379549449f / (float)D;
    const float f0 = exp2f(c * (float)(d + 0));
    const float f1 = exp2f(c * (float)(d + 1));
    const float f2 = exp2f(c * (float)(d + 2));
    const float f3 = exp2f(c * (float)(d + 3));

    int s   = blockIdx.x;
    int row = s * TPB + d4;

    // Prologue: entire row s (all 8 batches) in flight
    float4 A[B], N[B];
    #pragma unroll
    for (int b = 0; b < B; ++b) A[b] = __ldcs(&in[b * SD + row]);

    while (true) {
        // ---- half 1: consume A, prefetch into N ----
        {
            const int sn = s + GRID;
            const bool more = sn < S;
            const int rn = sn * TPB + d4;

            // Loads FIRST (read-issue continuity), MUFU hides under them
            if (more) {
                #pragma unroll
                for (int b = 0; b < B; ++b) N[b] = __ldcs(&in[b * SD + rn]);
            }

            const float fs = (float)s;
            float4 pe;                  // x,z even dims (sin); y,w odd (cos)
            pe.x = __sinf(fs * f0);
            pe.y = __cosf(fs * f1);
            pe.z = __sinf(fs * f2);
            pe.w = __cosf(fs * f3);

            store_row(out, row, A, pe);

            if (!more) break;
            s = sn; row = rn;
        }

        // ---- half 2: consume N, prefetch into A (no rotation copies) ----
        {
            const int sn = s + GRID;
            const bool more = sn < S;
            const int rn = sn * TPB + d4;

            if (more) {
                #pragma unroll
                for (int b = 0; b < B; ++b) A[b] = __ldcs(&in[b * SD + rn]);
            }

            const float fs = (float)s;
            float4 pe;
            pe.x = __sinf(fs * f0);
            pe.y = __cosf(fs * f1);
            pe.z = __sinf(fs * f2);
            pe.w = __cosf(fs * f3);

            store_row(out, row, N, pe);

            if (!more) break;
            s = sn; row = rn;
        }
    }
}

extern "C" void kernel_launch(void* const* d_in, const int* in_sizes, int n_in,
                              void* d_out, int out_size) {
    (void)in_sizes; (void)n_in; (void)out_size;
    const float4* in  = (const float4*)d_in[0];
    float4*       out = (float4*)d_out;
    pe_add_kernel<<<GRID, TPB>>>(in, out);
}

// round 12
// speedup vs baseline: 1.0590x; 1.0590x over previous
#include <cuda_runtime.h>
#include <cuda_bf16.h>

// out[b,s,d] = in[b,s,d] + pe(s,d)
//   pe(s,d) = sin(s * f(d)) if d even else cos(s * f(d)),  f(d) = 10000^(-2d/D)
//
// B=8, S=4096, D=1024, fp32. 268 MB/launch. Best: R10 = 45.6us (5.88 TB/s).
// R12 = R10 VERBATIM with one isolated edit: the 8-load next-row prefetch is
// issued ABOVE the pe MUFU computation inside the same single loop body
// (R11 tested this bundled with a ping-pong restructure that regressed even
// single-launch; this isolates the one plausibly-good half). The rotation
// copy stays — removing it was what broke R11's schedule.
// Held fixed: grid 592, 3/SM, .cs both ways, float4/256-thread map.

constexpr int D    = 1024;
constexpr int S    = 4096;
constexpr int B    = 8;
constexpr int TPB  = D / 4;       // 256 threads, one float4 of d each
constexpr int GRID = 4 * 148;     // 592 blocks, grid-stride over s
constexpr int SD   = S * TPB;     // float4 stride between batches

__global__ __launch_bounds__(TPB, 3)
void pe_add_kernel(const float4* __restrict__ in, float4* __restrict__ out) {
    const int d4 = threadIdx.x;
    const int d  = d4 * 4;

    // f(d+j) = exp2( -(d+j) * 2*log2(10000)/1024 ), row-independent
    const float c = -2.0f * 13.287712379549449f / (float)D;
    const float f0 = exp2f(c * (float)(d + 0));
    const float f1 = exp2f(c * (float)(d + 1));
    const float f2 = exp2f(c * (float)(d + 2));
    const float f3 = exp2f(c * (float)(d + 3));

    int s   = blockIdx.x;
    int row = s * TPB + d4;

    // Prologue: entire row s (all 8 batches) in flight
    float4 A[B];
    #pragma unroll
    for (int b = 0; b < B; ++b) A[b] = __ldcs(&in[b * SD + row]);

    while (true) {
        const int snext = s + GRID;
        const bool more = snext < S;
        const int rown  = snext * TPB + d4;

        // Prefetch FIRST: 8 loads issued before any MUFU/store work, so
        // read-issue never pauses at the top of the iteration and the MUFU
        // latency below hides under the in-flight loads.
        float4 N[B];
        if (more) {
            #pragma unroll
            for (int b = 0; b < B; ++b) N[b] = __ldcs(&in[b * SD + rown]);
        }

        const float fs = (float)s;
        float4 pe;                      // d%4==0: x,z even (sin); y,w odd (cos)
        pe.x = __sinf(fs * f0);
        pe.y = __cosf(fs * f1);
        pe.z = __sinf(fs * f2);
        pe.w = __cosf(fs * f3);

        // Store row s (depends only on A, already landed, and pe)
        #pragma unroll
        for (int b = 0; b < B; ++b) {
            float4 o;
            o.x = A[b].x + pe.x; o.y = A[b].y + pe.y;
            o.z = A[b].z + pe.z; o.w = A[b].w + pe.w;
            __stcs(&out[b * SD + row], o);
        }

        if (!more) break;
        #pragma unroll
        for (int b = 0; b < B; ++b) A[b] = N[b];
        s = snext;
        row = rown;
    }
}

extern "C" void kernel_launch(void* const* d_in, const int* in_sizes, int n_in,
                              void* d_out, int out_size) {
    (void)in_sizes; (void)n_in; (void)out_size;
    const float4* in  = (const float4*)d_in[0];
    float4*       out = (float4*)d_out;
    pe_add_kernel<<<GRID, TPB>>>(in, out);
}